// round 11
// baseline (speedup 1.0000x reference)
#include <cuda_runtime.h>

// SimpleQNN collapses analytically:
//   z[b,v]  = cos(rx[v]) * sin(x[b,v] - ry[v])
//   diagonal layers (CRZ, CZ, RZ) are pure phases -> no effect on probabilities
//   CNOT cascade -> parity masks: q_0 = prod_{1..15} z_v, q_w = prod_{0..w} z_v (w>=1)
//   q_w = S_w(b) * C_w  (sin/cos parts factor); C folded into W once:
//   W2[k,w] = W[k,w]*C_w;  out[b,k] = sum_w S_w(b)*W2[k,w] + bias[k]
//
// R6: libm trig dominated (7.9us) -> MUFU (5.2us).
// R7/R8: LDG vectorization + producer warp (4.54us); instr count no longer binding.
// R9 finding: remaining compressible cost = store tail (10 x STG.32 @ 40B stride
//   per thread = ~100 L1 wavefronts/warp). This round: 640-thread epilogue,
//   one output element per thread -> coalesced STG.32 (20 wavefronts total),
//   smem rows padded to pitch 17 for conflict-free LDS.

#define NW 16
#define BATCH 64
#define NOUT 10
#define PITCH 17                  // odd pitch -> conflict-free strided smem rows
#define NTHREADS (BATCH * NOUT)  // 640 = 20 warps

__global__ __launch_bounds__(NTHREADS, 1)
void simpleqnn_kernel(const float* __restrict__ x,
                      const float* __restrict__ ry,
                      const float* __restrict__ rx,
                      const float* __restrict__ W,
                      const float* __restrict__ bias,
                      float* __restrict__ out) {
    __shared__ float Ss[BATCH * PITCH];   // S[b][w] at b*PITCH+w
    __shared__ float w2s[NOUT * PITCH];   // W2[k][w] at k*PITCH+w
    __shared__ float bs[NOUT];

    const int t = threadIdx.x;

    if (t < BATCH) {
        // ---- phase 1a (2 warps): per-batch sin prefix masks ----
        float s[NW];
        const float4* xrow = reinterpret_cast<const float4*>(x + t * NW);
        const float4* ry4  = reinterpret_cast<const float4*>(ry);
#pragma unroll
        for (int i = 0; i < NW / 4; i++) {
            float4 a = xrow[i];
            float4 r = ry4[i];
            s[4*i+0] = __sinf(a.x - r.x);
            s[4*i+1] = __sinf(a.y - r.y);
            s[4*i+2] = __sinf(a.z - r.z);
            s[4*i+3] = __sinf(a.w - r.w);
        }
        float S[NW];
        float p = s[0];
#pragma unroll
        for (int w = 1; w < NW; w++) { p *= s[w]; S[w] = p; }
        float s0 = s[1];
#pragma unroll
        for (int v = 2; v < NW; v++) s0 *= s[v];
        S[0] = s0;
#pragma unroll
        for (int w = 0; w < NW; w++) Ss[t * PITCH + w] = S[w];
    } else if (t < BATCH + 32) {
        // ---- phase 1b (producer warp): cos prefixes folded into W ----
        const int lane = t - BATCH;
        float cv[NW];
        const float4* rx4 = reinterpret_cast<const float4*>(rx);
#pragma unroll
        for (int i = 0; i < NW / 4; i++) {
            float4 c = rx4[i];
            cv[4*i+0] = __cosf(c.x); cv[4*i+1] = __cosf(c.y);
            cv[4*i+2] = __cosf(c.z); cv[4*i+3] = __cosf(c.w);
        }
        float C[NW];
        float p = cv[0];
#pragma unroll
        for (int w = 1; w < NW; w++) { p *= cv[w]; C[w] = p; }
        float c0 = cv[1];
#pragma unroll
        for (int v = 2; v < NW; v++) c0 *= cv[v];
        C[0] = c0;

        for (int i = lane; i < NOUT * NW; i += 32) {
            int k = i >> 4, w = i & (NW - 1);
            w2s[k * PITCH + w] = W[i] * C[w];
        }
        if (lane < NOUT) bs[lane] = bias[lane];
    }

    __syncthreads();

    // ---- phase 2 (all 640 threads): one output element each, coalesced STG ----
    const int b = (t * 6554) >> 16;   // t / 10  (exact for t < 10486)
    const int k = t - b * NOUT;

    const float* Srow = &Ss[b * PITCH];
    const float* Wrow = &w2s[k * PITCH];
    float acc = bs[k];
#pragma unroll
    for (int w = 0; w < NW; w++) {
        acc = fmaf(Srow[w], Wrow[w], acc);
    }
    out[t] = acc;   // out[b*NOUT + k] == out[t] by construction
}

extern "C" void kernel_launch(void* const* d_in, const int* in_sizes, int n_in,
                              void* d_out, int out_size) {
    const float* x    = (const float*)d_in[0];   // (64,16)
    const float* ry   = (const float*)d_in[1];   // (16)
    const float* rx   = (const float*)d_in[2];   // (16)
    // d_in[3] = rz_params (unused: diagonal phases vanish in |psi|^2)
    // d_in[4] = crz_params (unused: same reason)
    const float* W    = (const float*)d_in[5];   // (10,16)
    const float* bias = (const float*)d_in[6];   // (10)
    float* out = (float*)d_out;                  // (64,10)

    simpleqnn_kernel<<<1, NTHREADS>>>(x, ry, rx, W, bias, out);
}

// round 15
// speedup vs baseline: 1.1026x; 1.1026x over previous
#include <cuda_runtime.h>

// SimpleQNN collapses analytically:
//   z[b,v]  = cos(rx[v]) * sin(x[b,v] - ry[v])
//   diagonal layers (CRZ, CZ, RZ) are pure phases -> no effect on probabilities
//   CNOT cascade -> parity masks: q_0 = prod_{1..15} z_v, q_w = prod_{0..w} z_v (w>=1)
//   q_w = S_w(b) * C_w; C folded into W once (producer warp, smem):
//   W2[k,w] = W[k,w]*C_w;  out[b,k] = sum_w S_w(b)*W2[k,w] + bias[k]
//
// R6:  libm trig dominated (7.9us) -> MUFU (5.2us).
// R7/8: LDG vectorization + producer warp -> 4.54us kernel / 6.21us total (best).
// R10: 640-thread coalesced-store epilogue REGRESSED (+0.9us): 20-warp barrier
//      + smem staging cost > store-tail savings. Reverted.
// R11: R9 structure + ONE tweak: epilogue stores as 5x STG.64 instead of
//      10x STG.32 (out+10b is 8B-aligned). No new threads, no new barriers.

#define NW 16
#define BATCH 64
#define NOUT 10
#define NTHREADS 96   // 2 batch warps + 1 producer warp

__global__ __launch_bounds__(NTHREADS, 1)
void simpleqnn_kernel(const float* __restrict__ x,
                      const float* __restrict__ ry,
                      const float* __restrict__ rx,
                      const float* __restrict__ W,
                      const float* __restrict__ bias,
                      float* __restrict__ out) {
    __shared__ float w2s[NOUT * NW];
    __shared__ float bs[NOUT];

    const int t = threadIdx.x;

    if (t >= BATCH) {
        // ---- producer warp: uniform cos prefixes folded into W ----
        const int lane = t - BATCH;  // 0..31
        float cv[NW];
        {
            const float4* rx4 = reinterpret_cast<const float4*>(rx);
#pragma unroll
            for (int i = 0; i < NW / 4; i++) {
                float4 c = rx4[i];
                cv[4*i+0] = __cosf(c.x); cv[4*i+1] = __cosf(c.y);
                cv[4*i+2] = __cosf(c.z); cv[4*i+3] = __cosf(c.w);
            }
        }
        float C[NW];
        float p = cv[0];
#pragma unroll
        for (int w = 1; w < NW; w++) { p *= cv[w]; C[w] = p; }
        float c0 = cv[1];
#pragma unroll
        for (int v = 2; v < NW; v++) c0 *= cv[v];
        C[0] = c0;

#pragma unroll
        for (int i = lane; i < NOUT * NW; i += 32)
            w2s[i] = W[i] * C[i & (NW - 1)];
        if (lane < NOUT) bs[lane] = bias[lane];

        __syncthreads();
        return;
    }

    // ---- batch warps: per-element sin parts (overlap producer's cos work) ----
    float s[NW];
    {
        const float4* xrow = reinterpret_cast<const float4*>(x + t * NW);
        const float4* ry4  = reinterpret_cast<const float4*>(ry);
#pragma unroll
        for (int i = 0; i < NW / 4; i++) {
            float4 a = xrow[i];
            float4 r = ry4[i];
            s[4*i+0] = __sinf(a.x - r.x);
            s[4*i+1] = __sinf(a.y - r.y);
            s[4*i+2] = __sinf(a.z - r.z);
            s[4*i+3] = __sinf(a.w - r.w);
        }
    }

    // Prefix-product masks over sin factors
    float S[NW];
    float p = s[0];
#pragma unroll
    for (int w = 1; w < NW; w++) { p *= s[w]; S[w] = p; }
    float s0 = s[1];
#pragma unroll
    for (int v = 2; v < NW; v++) s0 *= s[v];
    S[0] = s0;

    __syncthreads();   // W2 + bias ready in smem

    // Epilogue: out[b,k] = sum_w S_w * W2[k,w] + bias[k]  (broadcast LDS.128)
    float o[NOUT];
#pragma unroll
    for (int k = 0; k < NOUT; k++) {
        const float4* wrow = reinterpret_cast<const float4*>(&w2s[k * NW]);
        float acc = bs[k];
#pragma unroll
        for (int i = 0; i < NW / 4; i++) {
            float4 wv = wrow[i];
            acc = fmaf(S[4*i+0], wv.x, acc);
            acc = fmaf(S[4*i+1], wv.y, acc);
            acc = fmaf(S[4*i+2], wv.z, acc);
            acc = fmaf(S[4*i+3], wv.w, acc);
        }
        o[k] = acc;
    }

    // 5x STG.64 instead of 10x STG.32 (out + 10*t is 8-byte aligned)
    float2* orow = reinterpret_cast<float2*>(out + t * NOUT);
#pragma unroll
    for (int i = 0; i < NOUT / 2; i++) {
        orow[i] = make_float2(o[2*i], o[2*i+1]);
    }
}

extern "C" void kernel_launch(void* const* d_in, const int* in_sizes, int n_in,
                              void* d_out, int out_size) {
    const float* x    = (const float*)d_in[0];   // (64,16)
    const float* ry   = (const float*)d_in[1];   // (16)
    const float* rx   = (const float*)d_in[2];   // (16)
    // d_in[3] = rz_params (unused: diagonal phases vanish in |psi|^2)
    // d_in[4] = crz_params (unused: same reason)
    const float* W    = (const float*)d_in[5];   // (10,16)
    const float* bias = (const float*)d_in[6];   // (10)
    float* out = (float*)d_out;                  // (64,10)

    simpleqnn_kernel<<<1, NTHREADS>>>(x, ry, rx, W, bias, out);
}